// round 2
// baseline (speedup 1.0000x reference)
#include <cuda_runtime.h>
#include <cstdint>

// Problem dims
#define BB 1024
#define TT 512
#define DD 128
#define HH 256
#define CCLS 2
#define NROWS 8
#define NCTA (BB / NROWS)   // 128 CTAs
#define NTHR 256

// Transposed-weight scratch (device global; no allocations allowed)
// Layout (floats): WdhT[128][256], WdxT[128][128], WhT[256][128], WfT[128][128],
//                  WcT[256][128], WihT[256][1024], WhhT[256][1024]
#define OFF_WDH 0
#define OFF_WDX 32768
#define OFF_WH  49152
#define OFF_WF  81920
#define OFF_WC  98304
#define OFF_WIH 131072
#define OFF_WHH 393216
#define WT_TOTAL 655360
__device__ float g_wt[WT_TOTAL];

typedef unsigned long long u64;

__device__ __forceinline__ u64 ffma2(u64 a, u64 b, u64 c) {
    u64 d;
    asm("fma.rn.f32x2 %0, %1, %2, %3;" : "=l"(d) : "l"(a), "l"(b), "l"(c));
    return d;
}
__device__ __forceinline__ u64 dup2(float w) {
    u64 d; asm("mov.b64 %0, {%1, %1};" : "=l"(d) : "f"(w)); return d;
}
__device__ __forceinline__ void unpk(u64 v, float& lo, float& hi) {
    asm("mov.b64 {%0, %1}, %2;" : "=f"(lo), "=f"(hi) : "l"(v));
}
__device__ __forceinline__ float sigf(float x) { return 1.f / (1.f + __expf(-x)); }
__device__ __forceinline__ float tanh_fast(float x) { return 2.f / (1.f + __expf(-2.f * x)) - 1.f; }

// Generic transpose: W[N][K] -> WT[K][N]
__global__ void transpose_kernel(const float* __restrict__ W, float* __restrict__ WT, int N, int K) {
    int idx = blockIdx.x * blockDim.x + threadIdx.x;
    if (idx < N * K) {
        int n = idx / K, k = idx - n * K;
        WT[k * N + n] = W[idx];
    }
}

// Persistent RITS scan kernel. Each CTA owns 8 batch rows for all 512 steps.
// All per-row activations stored row-interleaved in smem: arr[k*8 + r], so that
// LDS.128 at [k*8] yields two packed f32x2 row-pairs for FFMA2.
__global__ void __launch_bounds__(NTHR, 1) rits_kernel(
    const float* __restrict__ values, const int* __restrict__ masks, const float* __restrict__ deltas,
    const float* __restrict__ bdh, const float* __restrict__ bdx,
    const float* __restrict__ bh,  const float* __restrict__ bf_,
    const float* __restrict__ bc,  const float* __restrict__ bih, const float* __restrict__ bhh,
    const float* __restrict__ Wo,  const float* __restrict__ bo,
    float* __restrict__ out)
{
    extern __shared__ float smem[];
    float* hs  = smem;            // [H*8]  LSTM hidden state
    float* cs  = hs  + 2048;      // [H*8]  LSTM cell state
    float* hd  = cs  + 2048;      // [H*8]  decayed hidden
    float* xs  = hd  + 2048;      // [D*8]
    float* msa = xs  + 1024;      // [D*8]  mask as float
    float* dsa = msa + 1024;      // [D*8]  deltas
    float* xh  = dsa + 1024;      // [D*8]
    float* gx  = xh  + 1024;      // [D*8]  gamma_x
    float* al  = gx  + 1024;      // [D*8]  alpha
    float* zh  = al  + 1024;      // [D*8]
    float* xcb = zh  + 1024;      // [D*8]  x_c
    float* ccs = xcb + 1024;      // [D*8]  c_c
    float* gt  = ccs + 1024;      // [4H*8] gates

    const int j = threadIdx.x;
    const int rowbase = blockIdx.x * NROWS;
    const float* wt = g_wt;
    float* out_imp = out + BB * CCLS;

    for (int i = j; i < 2048; i += NTHR) { hs[i] = 0.f; cs[i] = 0.f; }
    __syncthreads();

    for (int t = 0; t < TT; ++t) {
        // ---- phase 1: load x, m, d (gmem-coalesced) ----
        {
            const int base0 = rowbase * (TT * DD) + t * DD;
            #pragma unroll
            for (int i = 0; i < 4; ++i) {
                int idx = j + i * NTHR;            // 0..1023
                int r = idx >> 7, k = idx & 127;
                int g = base0 + r * (TT * DD) + k;
                xs [k * 8 + r] = values[g];
                msa[k * 8 + r] = (float)masks[g];
                dsa[k * 8 + r] = deltas[g];
            }
        }
        __syncthreads();

        // ---- phase 2: gamma_h (all 256 threads, 1 col each) + h decay ----
        {
            const int n = j;
            u64 a0 = dup2(bdh[n]), a1 = a0, a2 = a0, a3 = a0;
            #pragma unroll 8
            for (int k = 0; k < DD; ++k) {
                u64 wp = dup2(wt[OFF_WDH + k * HH + n]);
                const u64* ap = (const u64*)&dsa[k * 8];
                a0 = ffma2(ap[0], wp, a0); a1 = ffma2(ap[1], wp, a1);
                a2 = ffma2(ap[2], wp, a2); a3 = ffma2(ap[3], wp, a3);
            }
            float v[8];
            unpk(a0, v[0], v[1]); unpk(a1, v[2], v[3]);
            unpk(a2, v[4], v[5]); unpk(a3, v[6], v[7]);
            #pragma unroll
            for (int r = 0; r < 8; ++r) {
                float g = __expf(-fmaxf(v[r], 0.f));
                hd[n * 8 + r] = hs[n * 8 + r] * g;
            }
        }
        // gamma_x (threads < 128)
        if (j < DD) {
            const int n = j;
            u64 a0 = dup2(bdx[n]), a1 = a0, a2 = a0, a3 = a0;
            #pragma unroll 8
            for (int k = 0; k < DD; ++k) {
                u64 wp = dup2(wt[OFF_WDX + k * DD + n]);
                const u64* ap = (const u64*)&dsa[k * 8];
                a0 = ffma2(ap[0], wp, a0); a1 = ffma2(ap[1], wp, a1);
                a2 = ffma2(ap[2], wp, a2); a3 = ffma2(ap[3], wp, a3);
            }
            float v[8];
            unpk(a0, v[0], v[1]); unpk(a1, v[2], v[3]);
            unpk(a2, v[4], v[5]); unpk(a3, v[6], v[7]);
            #pragma unroll
            for (int r = 0; r < 8; ++r) gx[n * 8 + r] = __expf(-fmaxf(v[r], 0.f));
        }
        __syncthreads();

        // ---- phase 3: x_h = hd@Wh.T + bh (j<128)  |  alpha = [gx,m]@Wc.T + bc (j>=128) ----
        if (j < DD) {
            const int n = j;
            u64 a0 = dup2(bh[n]), a1 = a0, a2 = a0, a3 = a0;
            #pragma unroll 8
            for (int k = 0; k < HH; ++k) {
                u64 wp = dup2(wt[OFF_WH + k * DD + n]);
                const u64* ap = (const u64*)&hd[k * 8];
                a0 = ffma2(ap[0], wp, a0); a1 = ffma2(ap[1], wp, a1);
                a2 = ffma2(ap[2], wp, a2); a3 = ffma2(ap[3], wp, a3);
            }
            float v[8];
            unpk(a0, v[0], v[1]); unpk(a1, v[2], v[3]);
            unpk(a2, v[4], v[5]); unpk(a3, v[6], v[7]);
            #pragma unroll
            for (int r = 0; r < 8; ++r) xh[n * 8 + r] = v[r];
        } else {
            const int n = j - DD;
            u64 a0 = dup2(bc[n]), a1 = a0, a2 = a0, a3 = a0;
            #pragma unroll 8
            for (int k = 0; k < DD; ++k) {
                u64 wp = dup2(wt[OFF_WC + k * DD + n]);
                const u64* ap = (const u64*)&gx[k * 8];
                a0 = ffma2(ap[0], wp, a0); a1 = ffma2(ap[1], wp, a1);
                a2 = ffma2(ap[2], wp, a2); a3 = ffma2(ap[3], wp, a3);
            }
            #pragma unroll 8
            for (int k = 0; k < DD; ++k) {
                u64 wp = dup2(wt[OFF_WC + (k + DD) * DD + n]);
                const u64* ap = (const u64*)&msa[k * 8];
                a0 = ffma2(ap[0], wp, a0); a1 = ffma2(ap[1], wp, a1);
                a2 = ffma2(ap[2], wp, a2); a3 = ffma2(ap[3], wp, a3);
            }
            float v[8];
            unpk(a0, v[0], v[1]); unpk(a1, v[2], v[3]);
            unpk(a2, v[4], v[5]); unpk(a3, v[6], v[7]);
            #pragma unroll
            for (int r = 0; r < 8; ++r) al[n * 8 + r] = v[r];
        }
        __syncthreads();

        // ---- phase 3.5: x_c = m*x + (1-m)*x_h ----
        #pragma unroll
        for (int i = 0; i < 4; ++i) {
            int idx = j + i * NTHR;
            float mv = msa[idx];
            xcb[idx] = mv * xs[idx] + (1.f - mv) * xh[idx];
        }
        __syncthreads();

        // ---- phase 4: z_h = x_c@Wf.T + bf (row-split: 2 threads per col) ----
        {
            const int n = j & 127;
            const int half = j >> 7;   // 0: rows 0-3, 1: rows 4-7
            u64 a0 = dup2(bf_[n]), a1 = a0;
            #pragma unroll 8
            for (int k = 0; k < DD; ++k) {
                u64 wp = dup2(wt[OFF_WF + k * DD + n]);
                const u64* ap = (const u64*)&xcb[k * 8 + half * 4];
                a0 = ffma2(ap[0], wp, a0); a1 = ffma2(ap[1], wp, a1);
            }
            float v[4]; unpk(a0, v[0], v[1]); unpk(a1, v[2], v[3]);
            #pragma unroll
            for (int r = 0; r < 4; ++r) zh[n * 8 + half * 4 + r] = v[r];
        }
        __syncthreads();

        // ---- phase 5: c_h, c_c; write imputation (gmem-coalesced) ----
        {
            const int base0 = rowbase * (TT * DD) + t * DD;
            #pragma unroll
            for (int i = 0; i < 4; ++i) {
                int idx2 = j + i * NTHR;           // r*128 + k mapping
                int r = idx2 >> 7, k = idx2 & 127;
                int si = k * 8 + r;
                float a = al[si], zv = zh[si], xhv = xh[si], mv = msa[si], xv = xs[si];
                float ch = a * zv + (1.f - a) * xhv;
                float cc = mv * xv + (1.f - mv) * ch;
                ccs[si] = cc;
                out_imp[base0 + r * (TT * DD) + k] = cc;
            }
        }
        __syncthreads();

        // ---- phase 6: gates = [c_c,m]@Wih.T + bih + hd@Whh.T + bhh  (N=1024, 4 cols/thread) ----
        {
            const int n0 = j * 4;
            u64 acc[4][4];
            #pragma unroll
            for (int c = 0; c < 4; ++c) {
                u64 b = dup2(bih[n0 + c] + bhh[n0 + c]);
                acc[c][0] = b; acc[c][1] = b; acc[c][2] = b; acc[c][3] = b;
            }
            // K part 1: c_c (k = 0..127)
            #pragma unroll 4
            for (int k = 0; k < DD; ++k) {
                const u64* ap = (const u64*)&ccs[k * 8];
                u64 p0 = ap[0], p1 = ap[1], p2 = ap[2], p3 = ap[3];
                float4 w4 = *(const float4*)&wt[OFF_WIH + k * 1024 + n0];
                float wv[4] = {w4.x, w4.y, w4.z, w4.w};
                #pragma unroll
                for (int c = 0; c < 4; ++c) {
                    u64 wp = dup2(wv[c]);
                    acc[c][0] = ffma2(p0, wp, acc[c][0]);
                    acc[c][1] = ffma2(p1, wp, acc[c][1]);
                    acc[c][2] = ffma2(p2, wp, acc[c][2]);
                    acc[c][3] = ffma2(p3, wp, acc[c][3]);
                }
            }
            // K part 2: m (k = 128..255)
            #pragma unroll 4
            for (int k = 0; k < DD; ++k) {
                const u64* ap = (const u64*)&msa[k * 8];
                u64 p0 = ap[0], p1 = ap[1], p2 = ap[2], p3 = ap[3];
                float4 w4 = *(const float4*)&wt[OFF_WIH + (k + DD) * 1024 + n0];
                float wv[4] = {w4.x, w4.y, w4.z, w4.w};
                #pragma unroll
                for (int c = 0; c < 4; ++c) {
                    u64 wp = dup2(wv[c]);
                    acc[c][0] = ffma2(p0, wp, acc[c][0]);
                    acc[c][1] = ffma2(p1, wp, acc[c][1]);
                    acc[c][2] = ffma2(p2, wp, acc[c][2]);
                    acc[c][3] = ffma2(p3, wp, acc[c][3]);
                }
            }
            // K part 3: decayed h (k = 0..255)
            #pragma unroll 4
            for (int k = 0; k < HH; ++k) {
                const u64* ap = (const u64*)&hd[k * 8];
                u64 p0 = ap[0], p1 = ap[1], p2 = ap[2], p3 = ap[3];
                float4 w4 = *(const float4*)&wt[OFF_WHH + k * 1024 + n0];
                float wv[4] = {w4.x, w4.y, w4.z, w4.w};
                #pragma unroll
                for (int c = 0; c < 4; ++c) {
                    u64 wp = dup2(wv[c]);
                    acc[c][0] = ffma2(p0, wp, acc[c][0]);
                    acc[c][1] = ffma2(p1, wp, acc[c][1]);
                    acc[c][2] = ffma2(p2, wp, acc[c][2]);
                    acc[c][3] = ffma2(p3, wp, acc[c][3]);
                }
            }
            #pragma unroll
            for (int c = 0; c < 4; ++c) {
                float v[8];
                unpk(acc[c][0], v[0], v[1]); unpk(acc[c][1], v[2], v[3]);
                unpk(acc[c][2], v[4], v[5]); unpk(acc[c][3], v[6], v[7]);
                #pragma unroll
                for (int r = 0; r < 8; ++r) gt[(n0 + c) * 8 + r] = v[r];
            }
        }
        __syncthreads();

        // ---- phase 7: LSTM cell update (1 h-column per thread) ----
        {
            const int n = j;
            #pragma unroll
            for (int r = 0; r < 8; ++r) {
                float ig = sigf(gt[n * 8 + r]);
                float fg = sigf(gt[(n + HH) * 8 + r]);
                float gg = tanh_fast(gt[(n + 2 * HH) * 8 + r]);
                float og = sigf(gt[(n + 3 * HH) * 8 + r]);
                float cn = fg * cs[n * 8 + r] + ig * gg;
                cs[n * 8 + r] = cn;
                hs[n * 8 + r] = og * tanh_fast(cn);
            }
        }
        __syncthreads();
    }

    // ---- final: y_h = h@Wo.T + bo ----
    if (j < NROWS * CCLS) {
        int r = j >> 1, cl = j & 1;
        float acc = bo[cl];
        #pragma unroll 8
        for (int k = 0; k < HH; ++k) acc += hs[k * 8 + r] * Wo[cl * HH + k];
        out[(rowbase + r) * CCLS + cl] = acc;
    }
}

extern "C" void kernel_launch(void* const* d_in, const int* in_sizes, int n_in,
                              void* d_out, int out_size) {
    const float* values = (const float*)d_in[0];
    const int*   masks  = (const int*)  d_in[1];
    const float* deltas = (const float*)d_in[2];
    const float* Wdh = (const float*)d_in[3];
    const float* bdh = (const float*)d_in[4];
    const float* Wdx = (const float*)d_in[5];
    const float* bdx = (const float*)d_in[6];
    const float* Wh  = (const float*)d_in[7];
    const float* bh  = (const float*)d_in[8];
    const float* Wf  = (const float*)d_in[9];
    const float* bf_ = (const float*)d_in[10];
    const float* Wc  = (const float*)d_in[11];
    const float* bc  = (const float*)d_in[12];
    const float* Wih = (const float*)d_in[13];
    const float* bih = (const float*)d_in[14];
    const float* Whh = (const float*)d_in[15];
    const float* bhh = (const float*)d_in[16];
    const float* Wo  = (const float*)d_in[17];
    const float* bo  = (const float*)d_in[18];
    float* out = (float*)d_out;

    float* wt = nullptr;
    cudaGetSymbolAddress((void**)&wt, g_wt);

    // Prologue: transpose all weight matrices so the output index is contiguous
    // (coalesced weight streaming in the scan kernel).
    {
        struct { const float* W; int off, N, K; } jobs[7] = {
            {Wdh, OFF_WDH, HH, DD},
            {Wdx, OFF_WDX, DD, DD},
            {Wh,  OFF_WH,  DD, HH},
            {Wf,  OFF_WF,  DD, DD},
            {Wc,  OFF_WC,  DD, 2 * DD},
            {Wih, OFF_WIH, 4 * HH, 2 * DD},
            {Whh, OFF_WHH, 4 * HH, HH},
        };
        for (int i = 0; i < 7; ++i) {
            int tot = jobs[i].N * jobs[i].K;
            transpose_kernel<<<(tot + 255) / 256, 256>>>(jobs[i].W, wt + jobs[i].off,
                                                         jobs[i].N, jobs[i].K);
        }
    }

    size_t smem_bytes = 23552 * sizeof(float);  // 92 KB
    cudaFuncSetAttribute(rits_kernel, cudaFuncAttributeMaxDynamicSharedMemorySize,
                         (int)smem_bytes);
    rits_kernel<<<NCTA, NTHR, smem_bytes>>>(values, masks, deltas,
                                            bdh, bdx, bh, bf_, bc, bih, bhh,
                                            Wo, bo, out);
}

// round 4
// speedup vs baseline: 1.2581x; 1.2581x over previous
#include <cuda_runtime.h>
#include <cuda_bf16.h>
#include <cuda_fp16.h>
#include <cstdint>

// Problem dims
#define BB 1024
#define TT 512
#define DD 128
#define HH 256
#define CCLS 2
#define NROWS 8
#define NCTA (BB / NROWS)   // 128 CTAs
#define NTHR 512

// ---- weight scratch (device globals; no allocations allowed) ----
// Small matrices transposed, fp32: WdhT[128][256], WdxT[128][128], WhT[256][128],
// WfT[128][128], WcT[256][128]
#define OFF_WDH 0
#define OFF_WDX 32768
#define OFF_WH  49152
#define OFF_WF  81920
#define OFF_WC  98304
#define WT_SMALL 131072
__device__ float g_wt[WT_SMALL];
// Big matrices, fp16, k-pair packed: wih2[k2][n] u32 = (f16 W[2k2+1][n])<<16 | f16 W[2k2][n]
// wih2: [128][1024] (K=256: c_c rows then m rows), whh2: [128][1024] (K=256: h rows)
#define BOFF_WIH_U32 0
#define BOFF_WHH_U32 131072
__device__ uint32_t g_wtb_u[262144];
// Combined gate bias bih+bhh
__device__ float g_gb[4 * HH];

typedef unsigned long long u64;

__device__ __forceinline__ u64 ffma2(u64 a, u64 b, u64 c) {
    u64 d;
    asm("fma.rn.f32x2 %0, %1, %2, %3;" : "=l"(d) : "l"(a), "l"(b), "l"(c));
    return d;
}
__device__ __forceinline__ u64 dup2(float w) {
    u64 d; asm("mov.b64 %0, {%1, %1};" : "=l"(d) : "f"(w)); return d;
}
// unpack u32 of two fp16 -> two f32 (F2F with half-lane select in SASS)
__device__ __forceinline__ void h2_to_f2(uint32_t v, float& a, float& b) {
    asm("{\n\t.reg .b16 lo, hi;\n\tmov.b32 {lo, hi}, %2;\n\t"
        "cvt.f32.f16 %0, lo;\n\tcvt.f32.f16 %1, hi;\n\t}"
        : "=f"(a), "=f"(b) : "r"(v));
}
__device__ __forceinline__ void unpk(u64 v, float& lo, float& hi) {
    asm("mov.b64 {%0, %1}, %2;" : "=f"(lo), "=f"(hi) : "l"(v));
}
__device__ __forceinline__ float sigf(float x) { return 1.f / (1.f + __expf(-x)); }
__device__ __forceinline__ float tanh_fast(float x) { return 2.f / (1.f + __expf(-2.f * x)) - 1.f; }

// One packed k-pair of the gates GEMM: actbase points at activation rows for k (8 floats)
// then k+1 (8 floats). wv0 = column n0 weights (k, k+1), wv1 = column n0+1.
__device__ __forceinline__ void gates_k2(const float* actbase, uint32_t wv0, uint32_t wv1,
                                         u64* acc0, u64* acc1) {
    float w00, w01, w10, w11;
    h2_to_f2(wv0, w00, w01);
    h2_to_f2(wv1, w10, w11);
    u64 W00 = dup2(w00), W01 = dup2(w01), W10 = dup2(w10), W11 = dup2(w11);
    const u64* ap = (const u64*)actbase;
    #pragma unroll
    for (int p = 0; p < 4; ++p) {
        acc0[p] = ffma2(ap[p], W00, acc0[p]);
        acc1[p] = ffma2(ap[p], W10, acc1[p]);
        acc0[p] = ffma2(ap[4 + p], W01, acc0[p]);
        acc1[p] = ffma2(ap[4 + p], W11, acc1[p]);
    }
}

// ---- fused prologue: transposes + fp16 pack + bias combine, ONE launch ----
#define PREP_TOTAL (131072 + 262144 + 1024)
__global__ void prep_kernel(const float* __restrict__ Wdh, const float* __restrict__ Wdx,
                            const float* __restrict__ Wh,  const float* __restrict__ Wf,
                            const float* __restrict__ Wc,  const float* __restrict__ Wih,
                            const float* __restrict__ Whh, const float* __restrict__ bih,
                            const float* __restrict__ bhh) {
    int idx = blockIdx.x * blockDim.x + threadIdx.x;
    if (idx >= PREP_TOTAL) return;
    if (idx < 32768) {                     // WdhT[128][256] <- Wdh[256][128]
        int k = idx >> 8, n = idx & 255;
        g_wt[OFF_WDH + idx] = Wdh[n * 128 + k];
    } else if (idx < 49152) {              // WdxT[128][128] <- Wdx[128][128]
        int i = idx - 32768, k = i >> 7, n = i & 127;
        g_wt[idx] = Wdx[n * 128 + k];
    } else if (idx < 81920) {              // WhT[256][128] <- Wh[128][256]
        int i = idx - 49152, k = i >> 7, n = i & 127;
        g_wt[idx] = Wh[n * 256 + k];
    } else if (idx < 98304) {              // WfT[128][128] <- Wf[128][128]
        int i = idx - 81920, k = i >> 7, n = i & 127;
        g_wt[idx] = Wf[n * 128 + k];
    } else if (idx < 131072) {             // WcT[256][128] <- Wc[128][256]
        int i = idx - 98304, k = i >> 7, n = i & 127;
        g_wt[idx] = Wc[n * 256 + k];
    } else if (idx < 131072 + 131072) {    // wih2[k2][n] fp16-pair <- Wih[1024][256]
        int i = idx - 131072, k2 = i >> 10, n = i & 1023;
        uint32_t lo = __half_as_ushort(__float2half_rn(Wih[n * 256 + 2 * k2]));
        uint32_t hi = __half_as_ushort(__float2half_rn(Wih[n * 256 + 2 * k2 + 1]));
        g_wtb_u[BOFF_WIH_U32 + i] = lo | (hi << 16);
    } else if (idx < 131072 + 262144) {    // whh2[k2][n] fp16-pair <- Whh[1024][256]
        int i = idx - 131072 - 131072, k2 = i >> 10, n = i & 1023;
        uint32_t lo = __half_as_ushort(__float2half_rn(Whh[n * 256 + 2 * k2]));
        uint32_t hi = __half_as_ushort(__float2half_rn(Whh[n * 256 + 2 * k2 + 1]));
        g_wtb_u[BOFF_WHH_U32 + i] = lo | (hi << 16);
    } else {                               // combined gate bias
        int i = idx - 131072 - 262144;
        g_gb[i] = bih[i] + bhh[i];
    }
}

// ---- persistent RITS scan. Each CTA owns 8 batch rows for all 512 steps. ----
// Activations row-interleaved in smem: arr[k*8 + r] -> LDS.128 gives packed f32x2 row pairs.
__global__ void __launch_bounds__(NTHR, 1) rits_kernel(
    const float* __restrict__ values, const int* __restrict__ masks, const float* __restrict__ deltas,
    const float* __restrict__ bdh, const float* __restrict__ bdx,
    const float* __restrict__ bh,  const float* __restrict__ bf_,
    const float* __restrict__ bc,
    const float* __restrict__ Wo,  const float* __restrict__ bo,
    float* __restrict__ out)
{
    extern __shared__ float smem[];
    float* hs  = smem;            // [H*8]
    float* cs  = hs  + 2048;      // [H*8]
    float* hd  = cs  + 2048;      // [H*8]
    float* xs  = hd  + 2048;      // [D*8]
    float* msa = xs  + 1024;      // [D*8]
    float* dsa = msa + 1024;      // [D*8]
    float* xh  = dsa + 1024;      // [D*8]
    float* gx  = xh  + 1024;      // [D*8]
    float* al  = gx  + 1024;      // [D*8]
    float* zh  = al  + 1024;      // [D*8]
    float* xcb = zh  + 1024;      // [D*8]
    float* ccs = xcb + 1024;      // [D*8]
    float* gt  = ccs + 1024;      // [4H*8]

    const int j = threadIdx.x;
    const int rowbase = blockIdx.x * NROWS;
    const float* wt = g_wt;
    float* out_imp = out + BB * CCLS;

    for (int i = j; i < 2048; i += NTHR) { hs[i] = 0.f; cs[i] = 0.f; }

    // input prefetch registers (double-buffer in regs across steps)
    float pv[2], pm[2], pd[2];
    {
        const int base0 = rowbase * (TT * DD);
        #pragma unroll
        for (int i = 0; i < 2; ++i) {
            int idx = j + i * NTHR;
            int r = idx >> 7, k = idx & 127;
            int g = base0 + r * (TT * DD) + k;
            pv[i] = values[g]; pm[i] = (float)masks[g]; pd[i] = deltas[g];
        }
    }
    __syncthreads();

    for (int t = 0; t < TT; ++t) {
        // ---- phase 1: commit prefetched x, m, d to smem ----
        #pragma unroll
        for (int i = 0; i < 2; ++i) {
            int idx = j + i * NTHR;
            int r = idx >> 7, k = idx & 127;
            int si = k * 8 + r;
            xs[si] = pv[i]; msa[si] = pm[i]; dsa[si] = pd[i];
        }
        __syncthreads();

        // issue next step's input loads (consumed next iteration; DRAM latency hidden)
        if (t + 1 < TT) {
            const int base0 = rowbase * (TT * DD) + (t + 1) * DD;
            #pragma unroll
            for (int i = 0; i < 2; ++i) {
                int idx = j + i * NTHR;
                int r = idx >> 7, k = idx & 127;
                int g = base0 + r * (TT * DD) + k;
                pv[i] = values[g]; pm[i] = (float)masks[g]; pd[i] = deltas[g];
            }
        }

        // ---- phase 2: gamma_h + h decay (j<256) | gamma_x (j>=256) ----
        if (j < 256) {
            const int n = j;
            u64 a0 = dup2(bdh[n]), a1 = a0, a2 = a0, a3 = a0;
            #pragma unroll 8
            for (int k = 0; k < DD; ++k) {
                u64 wp = dup2(wt[OFF_WDH + k * HH + n]);
                const u64* ap = (const u64*)&dsa[k * 8];
                a0 = ffma2(ap[0], wp, a0); a1 = ffma2(ap[1], wp, a1);
                a2 = ffma2(ap[2], wp, a2); a3 = ffma2(ap[3], wp, a3);
            }
            float v[8];
            unpk(a0, v[0], v[1]); unpk(a1, v[2], v[3]);
            unpk(a2, v[4], v[5]); unpk(a3, v[6], v[7]);
            #pragma unroll
            for (int r = 0; r < 8; ++r) {
                float g = __expf(-fmaxf(v[r], 0.f));
                hd[n * 8 + r] = hs[n * 8 + r] * g;
            }
        } else {
            const int jj = j - 256;
            const int n = jj & 127, half = jj >> 7;       // 4 rows each
            u64 a0 = dup2(bdx[n]), a1 = a0;
            #pragma unroll 8
            for (int k = 0; k < DD; ++k) {
                u64 wp = dup2(wt[OFF_WDX + k * DD + n]);
                const u64* ap = (const u64*)&dsa[k * 8 + half * 4];
                a0 = ffma2(ap[0], wp, a0); a1 = ffma2(ap[1], wp, a1);
            }
            float v[4]; unpk(a0, v[0], v[1]); unpk(a1, v[2], v[3]);
            #pragma unroll
            for (int r = 0; r < 4; ++r) gx[n * 8 + half * 4 + r] = __expf(-fmaxf(v[r], 0.f));
        }
        __syncthreads();

        // ---- phase 3: x_h (j<256) | alpha (j>=256); 4 rows per thread ----
        if (j < 256) {
            const int n = j & 127, half = j >> 7;
            u64 a0 = dup2(bh[n]), a1 = a0;
            #pragma unroll 8
            for (int k = 0; k < HH; ++k) {
                u64 wp = dup2(wt[OFF_WH + k * DD + n]);
                const u64* ap = (const u64*)&hd[k * 8 + half * 4];
                a0 = ffma2(ap[0], wp, a0); a1 = ffma2(ap[1], wp, a1);
            }
            float v[4]; unpk(a0, v[0], v[1]); unpk(a1, v[2], v[3]);
            #pragma unroll
            for (int r = 0; r < 4; ++r) xh[n * 8 + half * 4 + r] = v[r];
        } else {
            const int jj = j - 256;
            const int n = jj & 127, half = jj >> 7;
            u64 a0 = dup2(bc[n]), a1 = a0;
            #pragma unroll 8
            for (int k = 0; k < DD; ++k) {
                u64 wp = dup2(wt[OFF_WC + k * DD + n]);
                const u64* ap = (const u64*)&gx[k * 8 + half * 4];
                a0 = ffma2(ap[0], wp, a0); a1 = ffma2(ap[1], wp, a1);
            }
            #pragma unroll 8
            for (int k = 0; k < DD; ++k) {
                u64 wp = dup2(wt[OFF_WC + (k + DD) * DD + n]);
                const u64* ap = (const u64*)&msa[k * 8 + half * 4];
                a0 = ffma2(ap[0], wp, a0); a1 = ffma2(ap[1], wp, a1);
            }
            float v[4]; unpk(a0, v[0], v[1]); unpk(a1, v[2], v[3]);
            #pragma unroll
            for (int r = 0; r < 4; ++r) al[n * 8 + half * 4 + r] = v[r];
        }
        __syncthreads();

        // ---- phase 3.5: x_c = m*x + (1-m)*x_h ----
        #pragma unroll
        for (int i = 0; i < 2; ++i) {
            int idx = j + i * NTHR;
            float mv = msa[idx];
            xcb[idx] = mv * xs[idx] + (1.f - mv) * xh[idx];
        }
        __syncthreads();

        // ---- phase 4: z_h = x_c@Wf.T + bf (2 rows per thread) ----
        {
            const int n = j & 127, q = j >> 7;            // q in 0..3
            u64 a0 = dup2(bf_[n]);
            #pragma unroll 8
            for (int k = 0; k < DD; ++k) {
                u64 wp = dup2(wt[OFF_WF + k * DD + n]);
                const u64* ap = (const u64*)&xcb[k * 8 + q * 2];
                a0 = ffma2(ap[0], wp, a0);
            }
            float v0, v1; unpk(a0, v0, v1);
            zh[n * 8 + q * 2 + 0] = v0;
            zh[n * 8 + q * 2 + 1] = v1;
        }
        __syncthreads();

        // ---- phase 5: c_h, c_c; write imputation ----
        {
            const int base0 = rowbase * (TT * DD) + t * DD;
            #pragma unroll
            for (int i = 0; i < 2; ++i) {
                int idx2 = j + i * NTHR;
                int r = idx2 >> 7, k = idx2 & 127;
                int si = k * 8 + r;
                float a = al[si], zv = zh[si], xhv = xh[si], mv = msa[si], xv = xs[si];
                float ch = a * zv + (1.f - a) * xhv;
                float cc = mv * xv + (1.f - mv) * ch;
                ccs[si] = cc;
                out_imp[base0 + r * (TT * DD) + k] = cc;
            }
        }
        __syncthreads();

        // ---- phase 6: gates (N=1024, fp16 k-paired weights, 2 cols/thread) ----
        {
            const int n0 = j << 1;
            u64 acc[2][4];
            {
                u64 b0 = dup2(g_gb[n0]), b1 = dup2(g_gb[n0 + 1]);
                #pragma unroll
                for (int p = 0; p < 4; ++p) { acc[0][p] = b0; acc[1][p] = b1; }
            }
            const uint32_t* wih2 = g_wtb_u + BOFF_WIH_U32;   // [128][1024]
            const uint32_t* whh2 = g_wtb_u + BOFF_WHH_U32;   // [128][1024]
            // K part 1: c_c (k2 = 0..63 -> k 0..127)
            #pragma unroll 4
            for (int k2 = 0; k2 < 64; ++k2) {
                uint2 wv = *(const uint2*)&wih2[k2 * 1024 + n0];
                gates_k2(&ccs[k2 * 16], wv.x, wv.y, acc[0], acc[1]);
            }
            // K part 2: m (k2 = 64..127)
            #pragma unroll 4
            for (int k2 = 0; k2 < 64; ++k2) {
                uint2 wv = *(const uint2*)&wih2[(k2 + 64) * 1024 + n0];
                gates_k2(&msa[k2 * 16], wv.x, wv.y, acc[0], acc[1]);
            }
            // K part 3: decayed h (k2 = 0..127 -> k 0..255)
            #pragma unroll 4
            for (int k2 = 0; k2 < 128; ++k2) {
                uint2 wv = *(const uint2*)&whh2[k2 * 1024 + n0];
                gates_k2(&hd[k2 * 16], wv.x, wv.y, acc[0], acc[1]);
            }
            #pragma unroll
            for (int c = 0; c < 2; ++c) {
                float v[8];
                unpk(acc[c][0], v[0], v[1]); unpk(acc[c][1], v[2], v[3]);
                unpk(acc[c][2], v[4], v[5]); unpk(acc[c][3], v[6], v[7]);
                #pragma unroll
                for (int r = 0; r < 8; ++r) gt[(n0 + c) * 8 + r] = v[r];
            }
        }
        __syncthreads();

        // ---- phase 7: LSTM cell update (2 threads per h-column, 4 rows each) ----
        {
            const int n = j & 255, half = j >> 8;
            #pragma unroll
            for (int r0 = 0; r0 < 4; ++r0) {
                int r = half * 4 + r0;
                float ig = sigf(gt[n * 8 + r]);
                float fg = sigf(gt[(n + HH) * 8 + r]);
                float gg = tanh_fast(gt[(n + 2 * HH) * 8 + r]);
                float og = sigf(gt[(n + 3 * HH) * 8 + r]);
                float cn = fg * cs[n * 8 + r] + ig * gg;
                cs[n * 8 + r] = cn;
                hs[n * 8 + r] = og * tanh_fast(cn);
            }
        }
        __syncthreads();
    }

    // ---- final: y_h = h@Wo.T + bo ----
    if (j < NROWS * CCLS) {
        int r = j >> 1, cl = j & 1;
        float acc = bo[cl];
        #pragma unroll 8
        for (int k = 0; k < HH; ++k) acc += hs[k * 8 + r] * Wo[cl * HH + k];
        out[(rowbase + r) * CCLS + cl] = acc;
    }
}

extern "C" void kernel_launch(void* const* d_in, const int* in_sizes, int n_in,
                              void* d_out, int out_size) {
    const float* values = (const float*)d_in[0];
    const int*   masks  = (const int*)  d_in[1];
    const float* deltas = (const float*)d_in[2];
    const float* Wdh = (const float*)d_in[3];
    const float* bdh = (const float*)d_in[4];
    const float* Wdx = (const float*)d_in[5];
    const float* bdx = (const float*)d_in[6];
    const float* Wh  = (const float*)d_in[7];
    const float* bh  = (const float*)d_in[8];
    const float* Wf  = (const float*)d_in[9];
    const float* bf_ = (const float*)d_in[10];
    const float* Wc  = (const float*)d_in[11];
    const float* bc  = (const float*)d_in[12];
    const float* Wih = (const float*)d_in[13];
    const float* bih = (const float*)d_in[14];
    const float* Whh = (const float*)d_in[15];
    const float* bhh = (const float*)d_in[16];
    const float* Wo  = (const float*)d_in[17];
    const float* bo  = (const float*)d_in[18];
    float* out = (float*)d_out;

    prep_kernel<<<(PREP_TOTAL + 255) / 256, 256>>>(Wdh, Wdx, Wh, Wf, Wc, Wih, Whh, bih, bhh);

    size_t smem_bytes = 23552 * sizeof(float);  // 92 KB
    cudaFuncSetAttribute(rits_kernel, cudaFuncAttributeMaxDynamicSharedMemorySize,
                         (int)smem_bytes);
    rits_kernel<<<NCTA, NTHR, smem_bytes>>>(values, masks, deltas,
                                            bdh, bdx, bh, bf_, bc,
                                            Wo, bo, out);
}